// round 2
// baseline (speedup 1.0000x reference)
#include <cuda_runtime.h>
#include <math.h>

#define EPS 1e-5f
#define HW 1024
#define NTH 256

// d=4 slice is sigmoid(W3 @ lrelu(bn2(W2 @ lrelu(bn1(0))))) — one 49-vector for ALL (b,h,w).
__device__ float g_d4vec[49];

__device__ __forceinline__ float lrelu(float v) { return v > 0.f ? v : 0.01f * v; }

// ---------------------------------------------------------------------------
// Kernel A: compute the constant d=4 output vector (input vector == 0)
// ---------------------------------------------------------------------------
__global__ void d4_kernel(const float* __restrict__ g1, const float* __restrict__ b1,
                          const float* __restrict__ rm1, const float* __restrict__ rv1,
                          const float* __restrict__ W2,
                          const float* __restrict__ g2, const float* __restrict__ b2,
                          const float* __restrict__ rm2, const float* __restrict__ rv2,
                          const float* __restrict__ W3)
{
    __shared__ float h1s[98], h2s[98];
    int t = threadIdx.x;
    if (t < 98) {
        float s1 = g1[t] * rsqrtf(rv1[t] + EPS);
        float o1 = b1[t] - rm1[t] * s1;
        h1s[t] = lrelu(o1);             // conv(0)*s1 + o1
    }
    __syncthreads();
    if (t < 98) {
        float acc = 0.f;
        for (int k = 0; k < 98; k++) acc = fmaf(W2[t * 98 + k], h1s[k], acc);
        float s2 = g2[t] * rsqrtf(rv2[t] + EPS);
        float o2 = b2[t] - rm2[t] * s2;
        h2s[t] = lrelu(fmaf(acc, s2, o2));
    }
    __syncthreads();
    if (t < 49) {
        float acc = 0.f;
        for (int k = 0; k < 98; k++) acc = fmaf(W3[t * 98 + k], h2s[k], acc);
        g_d4vec[t] = 1.f / (1.f + expf(-acc));
    }
}

// ---------------------------------------------------------------------------
// Kernel B: broadcast the d=4 vector. One block per (b,a), float4 stores.
// out[((b*49+a)*9+4)*1024 + pos] = d4vec[a]
// ---------------------------------------------------------------------------
__global__ void bcast_kernel(float* __restrict__ out)
{
    int blk = blockIdx.x;                 // b*49 + a
    float v = g_d4vec[blk % 49];
    float4 v4 = make_float4(v, v, v, v);
    ((float4*)(out + ((size_t)blk * 9 + 4) * HW))[threadIdx.x] = v4;
}

// ---------------------------------------------------------------------------
// Kernel C: main. One CTA per (b, dp), dp=0..3 -> dil=4-dp, writes slices dp and 8-dp.
// ---------------------------------------------------------------------------
// smem layout (floats):
//   xs    [1024]
//   W1T   [49*100]   W1T[a*100+o] = W1[o*49+a]
//   W2T   [98*100]   W2T[k*100+o] = W2[o*98+k]
//   W3T   [98*52]    W3T[k*52+o]  = W3[o*98+k]
//   s1s/o1s/s2s/o2s [98 each]
//   cs    [49]       center values per unfold offset
//   hbuf  [256*101]  per-thread scratch slice (101 mod 32 = 5 -> conflict-free)
#define SM_FLOATS (1024 + 49*100 + 98*100 + 98*52 + 4*98 + 49 + 256*101)

__global__ __launch_bounds__(NTH, 1) void main_kernel(
    const float* __restrict__ x,
    const float* __restrict__ W1,
    const float* __restrict__ g1, const float* __restrict__ b1,
    const float* __restrict__ rm1, const float* __restrict__ rv1,
    const float* __restrict__ W2,
    const float* __restrict__ g2, const float* __restrict__ b2,
    const float* __restrict__ rm2, const float* __restrict__ rv2,
    const float* __restrict__ W3,
    float* __restrict__ out)
{
    extern __shared__ float sm[];
    float* xs  = sm;
    float* W1T = xs + 1024;
    float* W2T = W1T + 49 * 100;
    float* W3T = W2T + 98 * 100;
    float* s1s = W3T + 98 * 52;
    float* o1s = s1s + 98;
    float* s2s = o1s + 98;
    float* o2s = s2s + 98;
    float* cs  = o2s + 98;
    float* hbuf = cs + 49;

    const int tid = threadIdx.x;
    const int b  = blockIdx.x >> 2;
    const int dp = blockIdx.x & 3;
    const int dil = 4 - dp;

    // ---- stage inputs / transpose weights into smem ----
    for (int i = tid; i < 1024; i += NTH) xs[i] = x[b * 1024 + i];
    for (int i = tid; i < 98 * 49; i += NTH) { int o = i / 49, a = i % 49; W1T[a * 100 + o] = W1[i]; }
    for (int i = tid; i < 98 * 98; i += NTH) { int o = i / 98, k = i % 98; W2T[k * 100 + o] = W2[i]; }
    for (int i = tid; i < 49 * 98; i += NTH) { int o = i / 98, k = i % 98; W3T[k * 52 + o] = W3[i]; }
    if (tid < 98) {
        float s1 = g1[tid] * rsqrtf(rv1[tid] + EPS);
        s1s[tid] = s1; o1s[tid] = b1[tid] - rm1[tid] * s1;
        float s2 = g2[tid] * rsqrtf(rv2[tid] + EPS);
        s2s[tid] = s2; o2s[tid] = b2[tid] - rm2[tid] * s2;
    }
    __syncthreads();
    if (tid < 49) {
        // center = flattened position 512 => (h,w) = (16, 0)
        int i = tid / 7, j = tid % 7;
        int hh = 16 + (i - 3) * dil, ww = (j - 3) * dil;
        cs[tid] = ((unsigned)hh < 32u && (unsigned)ww < 32u) ? xs[hh * 32 + ww] : 0.f;
    }
    __syncthreads();

    float* my = hbuf + tid * 101;
    const size_t obase = (size_t)b * 49 * 9 * HW;
    const size_t dlo = (size_t)dp * HW;
    const size_t dhi = (size_t)(8 - dp) * HW;

    for (int p = tid; p < HW; p += NTH) {
        const int h = p >> 5, w = p & 31;

        // ---- layer 1: 49 -> 98 (gather t on the fly) ----
        float h1[98];
        #pragma unroll
        for (int o = 0; o < 98; o++) h1[o] = 0.f;
        {
            int a = 0;
            for (int i = 0; i < 7; i++) {
                const int hh = h + (i - 3) * dil;
                const bool hok = (unsigned)hh < 32u;
                for (int j = 0; j < 7; j++, a++) {
                    const int ww = w + (j - 3) * dil;
                    float tv = (hok && (unsigned)ww < 32u) ? xs[hh * 32 + ww] : 0.f;
                    tv -= cs[a];
                    const float* row = &W1T[a * 100];
                    #pragma unroll
                    for (int o = 0; o < 98; o++) h1[o] = fmaf(row[o], tv, h1[o]);
                }
            }
        }
        #pragma unroll
        for (int o = 0; o < 98; o++) {
            float v = fmaf(h1[o], s1s[o], o1s[o]);
            my[o] = lrelu(v);
        }

        // ---- layer 2: 98 -> 98 ----
        float h2[98];
        #pragma unroll
        for (int o = 0; o < 98; o++) h2[o] = 0.f;
        for (int k = 0; k < 98; k++) {
            const float hk = my[k];
            const float* row = &W2T[k * 100];
            #pragma unroll
            for (int o = 0; o < 98; o++) h2[o] = fmaf(row[o], hk, h2[o]);
        }
        #pragma unroll
        for (int o = 0; o < 98; o++) {
            float v = fmaf(h2[o], s2s[o], o2s[o]);
            my[o] = lrelu(v);
        }

        // ---- layer 3: 98 -> 49 + sigmoid ----
        float acc[49];
        #pragma unroll
        for (int o = 0; o < 49; o++) acc[o] = 0.f;
        for (int k = 0; k < 98; k++) {
            const float hk = my[k];
            const float* row = &W3T[k * 52];
            #pragma unroll
            for (int o = 0; o < 49; o++) acc[o] = fmaf(row[o], hk, acc[o]);
        }

        #pragma unroll
        for (int o = 0; o < 49; o++) {
            const float v = 1.f / (1.f + expf(-acc[o]));
            const size_t co = obase + (size_t)o * 9 * HW + p;
            out[co + dlo] = v;   // slice d = dp
            out[co + dhi] = v;   // mirrored slice d = 8-dp
        }
    }
}

// ---------------------------------------------------------------------------
extern "C" void kernel_launch(void* const* d_in, const int* in_sizes, int n_in,
                              void* d_out, int out_size)
{
    const float* x   = (const float*)d_in[0];
    const float* W1  = (const float*)d_in[1];
    const float* g1  = (const float*)d_in[2];
    const float* b1  = (const float*)d_in[3];
    const float* rm1 = (const float*)d_in[4];
    const float* rv1 = (const float*)d_in[5];
    const float* W2  = (const float*)d_in[6];
    const float* g2  = (const float*)d_in[7];
    const float* b2  = (const float*)d_in[8];
    const float* rm2 = (const float*)d_in[9];
    const float* rv2 = (const float*)d_in[10];
    const float* W3  = (const float*)d_in[11];
    float* out = (float*)d_out;

    const int B = in_sizes[0] / HW;   // x is (B,1,32,32)

    (void)n_in; (void)out_size;

    const int smem_bytes = SM_FLOATS * sizeof(float);
    cudaFuncSetAttribute(main_kernel, cudaFuncAttributeMaxDynamicSharedMemorySize, smem_bytes);

    d4_kernel<<<1, 128>>>(g1, b1, rm1, rv1, W2, g2, b2, rm2, rv2, W3);
    bcast_kernel<<<B * 49, 256>>>(out);
    main_kernel<<<B * 4, NTH, smem_bytes>>>(x, W1, g1, b1, rm1, rv1,
                                            W2, g2, b2, rm2, rv2, W3, out);
}

// round 4
// speedup vs baseline: 2.2602x; 2.2602x over previous
#include <cuda_runtime.h>
#include <math.h>
#include <stdint.h>

#define EPS 1e-5f
#define HW 1024
#define NTH 256
#define LD  104   // floats; 104 % 32 == 8 -> conflict-free fragment LDS
#define LD3 72    // 72 % 32 == 8

__device__ __forceinline__ float lrelu(float v) { return v > 0.f ? v : 0.01f * v; }

__device__ __forceinline__ uint32_t tf32r(float x) {  // round-to-nearest tf32 (bits)
    uint32_t u; asm("cvt.rna.tf32.f32 %0, %1;" : "=r"(u) : "f"(x)); return u;
}

// D += A(16x8 tf32, row) @ B(8x8 tf32, col)
__device__ __forceinline__ void mma8(float c[4], uint32_t a0, uint32_t a1, uint32_t a2, uint32_t a3,
                                     uint32_t b0, uint32_t b1)
{
    asm volatile("mma.sync.aligned.m16n8k8.row.col.f32.tf32.tf32.f32 "
                 "{%0,%1,%2,%3}, {%4,%5,%6,%7}, {%8,%9}, {%0,%1,%2,%3};"
                 : "+f"(c[0]), "+f"(c[1]), "+f"(c[2]), "+f"(c[3])
                 : "r"(a0), "r"(a1), "r"(a2), "r"(a3), "r"(b0), "r"(b1));
}

// ============================ d=4 constant slice ============================
__device__ float g_d4vec[49];

__global__ void d4_kernel(const float* __restrict__ g1, const float* __restrict__ b1,
                          const float* __restrict__ rm1, const float* __restrict__ rv1,
                          const float* __restrict__ W2,
                          const float* __restrict__ g2, const float* __restrict__ b2,
                          const float* __restrict__ rm2, const float* __restrict__ rv2,
                          const float* __restrict__ W3)
{
    __shared__ float h1s[98], h2s[98];
    int t = threadIdx.x;
    if (t < 98) {
        float s1 = g1[t] * rsqrtf(rv1[t] + EPS);
        h1s[t] = lrelu(b1[t] - rm1[t] * s1);
    }
    __syncthreads();
    if (t < 98) {
        float acc = 0.f;
        for (int k = 0; k < 98; k++) acc = fmaf(W2[t * 98 + k], h1s[k], acc);
        float s2 = g2[t] * rsqrtf(rv2[t] + EPS);
        h2s[t] = lrelu(fmaf(acc, s2, b2[t] - rm2[t] * s2));
    }
    __syncthreads();
    if (t < 49) {
        float acc = 0.f;
        for (int k = 0; k < 98; k++) acc = fmaf(W3[t * 98 + k], h2s[k], acc);
        g_d4vec[t] = 1.f / (1.f + expf(-acc));
    }
}

__global__ void bcast_kernel(float* __restrict__ out)
{
    int blk = blockIdx.x;                 // b*49 + a
    float v = g_d4vec[blk % 49];
    ((float4*)(out + ((size_t)blk * 9 + 4) * HW))[threadIdx.x] = make_float4(v, v, v, v);
}

// ============================ warp-level GEMM pieces ============================
// A: smem, ld=LD, rows m-tile of 16. W: smem K-major [k][n], ld=LDW.
// C[n][4] per mma C-fragment. A split hi/lo tf32 (2 passes) for precision.
template <int KSTEPS, int NTILES, int LDW>
__device__ __forceinline__ void warp_gemm(const float* __restrict__ A,
                                          const float* __restrict__ W,
                                          float C[NTILES][4], int g, int t)
{
    #pragma unroll
    for (int n = 0; n < NTILES; n++) { C[n][0] = 0.f; C[n][1] = 0.f; C[n][2] = 0.f; C[n][3] = 0.f; }

    for (int ks = 0; ks < KSTEPS; ks++) {
        const int k0 = ks * 8;
        const float a0 = A[g * LD + k0 + t];
        const float a1 = A[(g + 8) * LD + k0 + t];
        const float a2 = A[g * LD + k0 + t + 4];
        const float a3 = A[(g + 8) * LD + k0 + t + 4];
        const uint32_t h0 = tf32r(a0), h1 = tf32r(a1), h2 = tf32r(a2), h3 = tf32r(a3);
        const uint32_t l0 = tf32r(a0 - __uint_as_float(h0));
        const uint32_t l1 = tf32r(a1 - __uint_as_float(h1));
        const uint32_t l2 = tf32r(a2 - __uint_as_float(h2));
        const uint32_t l3 = tf32r(a3 - __uint_as_float(h3));

        uint32_t b0[NTILES], b1[NTILES];
        #pragma unroll
        for (int n = 0; n < NTILES; n++) {
            b0[n] = __float_as_uint(W[(k0 + t) * LDW + n * 8 + g]);
            b1[n] = __float_as_uint(W[(k0 + t + 4) * LDW + n * 8 + g]);
        }
        #pragma unroll
        for (int n = 0; n < NTILES; n++) mma8(C[n], h0, h1, h2, h3, b0[n], b1[n]);
        #pragma unroll
        for (int n = 0; n < NTILES; n++) mma8(C[n], l0, l1, l2, l3, b0[n], b1[n]);
    }
}

// bn + leaky-relu epilogue: C fragments -> smem buffer (ld=LD)
template <int NTILES>
__device__ __forceinline__ void epi_bn(float C[NTILES][4],
                                       const float* __restrict__ sc, const float* __restrict__ os,
                                       float* __restrict__ outb, int g, int t)
{
    #pragma unroll
    for (int n = 0; n < NTILES; n++) {
        const int c0 = n * 8 + 2 * t;
        const float s0 = sc[c0], s1 = sc[c0 + 1];
        const float q0 = os[c0], q1 = os[c0 + 1];
        float y0 = lrelu(fmaf(C[n][0], s0, q0));
        float y1 = lrelu(fmaf(C[n][1], s1, q1));
        float y2 = lrelu(fmaf(C[n][2], s0, q0));
        float y3 = lrelu(fmaf(C[n][3], s1, q1));
        *(float2*)&outb[g * LD + c0]       = make_float2(y0, y1);
        *(float2*)&outb[(g + 8) * LD + c0] = make_float2(y2, y3);
    }
}

// ============================ main kernel ============================
// smem floats:
//  xs[1024] | W1t[56*LD] | W2t[104*LD] | W3t[104*LD3] | s1,o1,s2,o2[104 ea] | cs[56]
//  bufs[8 warps * 2 * 16*LD]
#define SM_FLOATS (1024 + 56*LD + 104*LD + 104*LD3 + 4*104 + 56 + 8*2*16*LD)

__global__ __launch_bounds__(NTH, 1) void main_kernel(
    const float* __restrict__ x,
    const float* __restrict__ W1,
    const float* __restrict__ g1, const float* __restrict__ b1,
    const float* __restrict__ rm1, const float* __restrict__ rv1,
    const float* __restrict__ W2,
    const float* __restrict__ g2, const float* __restrict__ b2,
    const float* __restrict__ rm2, const float* __restrict__ rv2,
    const float* __restrict__ W3,
    float* __restrict__ out)
{
    extern __shared__ float sm[];
    float* xs  = sm;
    float* W1t = xs + 1024;
    float* W2t = W1t + 56 * LD;
    float* W3t = W2t + 104 * LD;
    float* s1s = W3t + 104 * LD3;
    float* o1s = s1s + 104;
    float* s2s = o1s + 104;
    float* o2s = s2s + 104;
    float* cs  = o2s + 104;
    float* bufs = cs + 56;

    const int tid  = threadIdx.x;
    const int wid  = tid >> 5;
    const int lane = tid & 31;
    const int g = lane >> 2, t = lane & 3;
    const int b  = blockIdx.x >> 2;
    const int dp = blockIdx.x & 3;
    const int dil = 4 - dp;

    // ---- stage x + weights (tf32-rounded, K-major) + bn consts ----
    for (int i = tid; i < 1024; i += NTH) xs[i] = x[b * 1024 + i];
    for (int i = tid; i < 56 * LD; i += NTH) {            // W1t[k][n] = W1[n][k]
        int k = i / LD, n = i % LD;
        float v = (k < 49 && n < 98) ? W1[n * 49 + k] : 0.f;
        W1t[i] = __uint_as_float(tf32r(v));
    }
    for (int i = tid; i < 104 * LD; i += NTH) {           // W2t[k][n] = W2[n][k]
        int k = i / LD, n = i % LD;
        float v = (k < 98 && n < 98) ? W2[n * 98 + k] : 0.f;
        W2t[i] = __uint_as_float(tf32r(v));
    }
    for (int i = tid; i < 104 * LD3; i += NTH) {          // W3t[k][n] = W3[n][k]
        int k = i / LD3, n = i % LD3;
        float v = (k < 98 && n < 49) ? W3[n * 98 + k] : 0.f;
        W3t[i] = __uint_as_float(tf32r(v));
    }
    if (tid < 104) {
        if (tid < 98) {
            float s1 = g1[tid] * rsqrtf(rv1[tid] + EPS);
            s1s[tid] = s1; o1s[tid] = b1[tid] - rm1[tid] * s1;
            float s2 = g2[tid] * rsqrtf(rv2[tid] + EPS);
            s2s[tid] = s2; o2s[tid] = b2[tid] - rm2[tid] * s2;
        } else {
            s1s[tid] = 0.f; o1s[tid] = 0.f; s2s[tid] = 0.f; o2s[tid] = 0.f;
        }
    }
    __syncthreads();
    if (tid < 49) {   // center = flat pos 512 -> (h,w) = (16,0)
        int i = tid / 7, j = tid % 7;
        int hh = 16 + (i - 3) * dil, ww = (j - 3) * dil;
        cs[tid] = ((unsigned)hh < 32u && (unsigned)ww < 32u) ? xs[hh * 32 + ww] : 0.f;
    }
    __syncthreads();

    float* buf0 = bufs + wid * (2 * 16 * LD);
    float* buf1 = buf0 + 16 * LD;

    const size_t obase = (size_t)b * 49 * 9 * HW;
    const size_t dlo = (size_t)dp * HW;
    const size_t dhi = (size_t)(8 - dp) * HW;

    // per-lane tap constants for the T build (cols lane and lane+32)
    const int a0c = lane,  a1c = lane + 32;
    const int ii0 = a0c / 7, jj0 = a0c % 7;
    const int ii1 = a1c / 7, jj1 = a1c % 7;
    const float c0v = (a0c < 49) ? cs[a0c] : 0.f;
    const float c1v = (a1c < 49) ? cs[a1c] : 0.f;

    // ---- warps are fully independent: each owns m-tiles wid, wid+8, ... ----
    for (int mt = wid; mt < 64; mt += 8) {
        const int rbase = mt * 16;

        // build T tile (16 x 56, cols >= 49 zero) into buf0
        #pragma unroll
        for (int r = 0; r < 16; r++) {
            const int p = rbase + r;
            const int h = p >> 5, w = p & 31;
            float v0 = 0.f, v1 = 0.f;
            if (a0c < 49) {
                int hh = h + (ii0 - 3) * dil, ww = w + (jj0 - 3) * dil;
                float xv = ((unsigned)hh < 32u && (unsigned)ww < 32u) ? xs[hh * 32 + ww] : 0.f;
                v0 = xv - c0v;
            }
            if (a1c < 49) {
                int hh = h + (ii1 - 3) * dil, ww = w + (jj1 - 3) * dil;
                float xv = ((unsigned)hh < 32u && (unsigned)ww < 32u) ? xs[hh * 32 + ww] : 0.f;
                v1 = xv - c1v;
            }
            buf0[r * LD + a0c] = v0;
            if (a1c < 56) buf0[r * LD + a1c] = v1;
        }
        __syncwarp();

        // layer 1: [16x56] @ W1t -> C1[13], bn1+lrelu -> buf1
        {
            float C1[13][4];
            warp_gemm<7, 13, LD>(buf0, W1t, C1, g, t);
            epi_bn<13>(C1, s1s, o1s, buf1, g, t);
        }
        __syncwarp();

        // layer 2: [16x104] @ W2t -> C2[13], bn2+lrelu -> buf0
        {
            float C2[13][4];
            warp_gemm<13, 13, LD>(buf1, W2t, C2, g, t);
            epi_bn<13>(C2, s2s, o2s, buf0, g, t);
        }
        __syncwarp();

        // layer 3: [16x104] @ W3t -> C3[7], sigmoid -> global (mirrored d slices)
        {
            float C3[7][4];
            warp_gemm<13, 7, LD3>(buf0, W3t, C3, g, t);

            #pragma unroll
            for (int n = 0; n < 7; n++) {
                const int c0 = n * 8 + 2 * t;
                if (c0 < 49) {
                    float v0 = __fdividef(1.f, 1.f + __expf(-C3[n][0]));
                    float v2 = __fdividef(1.f, 1.f + __expf(-C3[n][2]));
                    const size_t co = obase + (size_t)c0 * 9 * HW;
                    const size_t p0 = co + (size_t)(rbase + g);
                    const size_t p2 = co + (size_t)(rbase + g + 8);
                    out[p0 + dlo] = v0; out[p0 + dhi] = v0;
                    out[p2 + dlo] = v2; out[p2 + dhi] = v2;
                }
                if (c0 + 1 < 49) {
                    float v1 = __fdividef(1.f, 1.f + __expf(-C3[n][1]));
                    float v3 = __fdividef(1.f, 1.f + __expf(-C3[n][3]));
                    const size_t co = obase + (size_t)(c0 + 1) * 9 * HW;
                    const size_t p1 = co + (size_t)(rbase + g);
                    const size_t p3 = co + (size_t)(rbase + g + 8);
                    out[p1 + dlo] = v1; out[p1 + dhi] = v1;
                    out[p3 + dlo] = v3; out[p3 + dhi] = v3;
                }
            }
        }
        __syncwarp();   // buf0 fully read before next tile's T build
    }
}

// ---------------------------------------------------------------------------
extern "C" void kernel_launch(void* const* d_in, const int* in_sizes, int n_in,
                              void* d_out, int out_size)
{
    const float* x   = (const float*)d_in[0];
    const float* W1  = (const float*)d_in[1];
    const float* g1  = (const float*)d_in[2];
    const float* b1  = (const float*)d_in[3];
    const float* rm1 = (const float*)d_in[4];
    const float* rv1 = (const float*)d_in[5];
    const float* W2  = (const float*)d_in[6];
    const float* g2  = (const float*)d_in[7];
    const float* b2  = (const float*)d_in[8];
    const float* rm2 = (const float*)d_in[9];
    const float* rv2 = (const float*)d_in[10];
    const float* W3  = (const float*)d_in[11];
    float* out = (float*)d_out;

    const int B = in_sizes[0] / HW;
    (void)n_in; (void)out_size;

    const int smem_bytes = SM_FLOATS * sizeof(float);
    cudaFuncSetAttribute(main_kernel, cudaFuncAttributeMaxDynamicSharedMemorySize, smem_bytes);

    d4_kernel<<<1, 128>>>(g1, b1, rm1, rv1, W2, g2, b2, rm2, rv2, W3);
    bcast_kernel<<<B * 49, 256>>>(out);
    main_kernel<<<B * 4, NTH, smem_bytes>>>(x, W1, g1, b1, rm1, rv1,
                                            W2, g2, b2, rm2, rv2, W3, out);
}